// round 17
// baseline (speedup 1.0000x reference)
#include <cuda_runtime.h>
#include <stdint.h>

#define DW    32
#define K2D   64
#define NW    512
#define BATCH 2048
#define WPAD  68     // W smem pitch (floats): banks 4g+tig distinct -> conflict-free
#define XP    520    // x stage pitch (floats), ==8 mod 32: frag banks 8*tig+g distinct
#define TP    516    // transpose buffer pitch (floats), ==4 mod 32

__device__ __forceinline__ uint32_t tf32_rna(float x) {
    uint32_t r; asm("cvt.rna.tf32.f32 %0, %1;" : "=r"(r) : "f"(x)); return r;
}

// D += A(tf32) * B(tf32), m16n8k8, A row-major, B col-major
#define HMMA(d, A0, A1, A2, A3, B0, B1) \
    asm volatile("mma.sync.aligned.m16n8k8.row.col.f32.tf32.tf32.f32 " \
        "{%0,%1,%2,%3}, {%4,%5,%6,%7}, {%8,%9}, {%0,%1,%2,%3};" \
        : "+f"((d)[0]), "+f"((d)[1]), "+f"((d)[2]), "+f"((d)[3]) \
        : "r"(A0), "r"(A1), "r"(A2), "r"(A3), "r"(B0), "r"(B1))

#define CP_ASYNC16(dst_u32, src) \
    asm volatile("cp.async.cg.shared.global [%0], [%1], 16;" \
                 :: "r"(dst_u32), "l"(src) : "memory")
#define CP_COMMIT() asm volatile("cp.async.commit_group;" ::: "memory")
#define CP_WAIT1()  asm volatile("cp.async.wait_group 1;" ::: "memory")
#define CP_WAIT0()  asm volatile("cp.async.wait_group 0;" ::: "memory")

__global__ __launch_bounds__(512, 3)
void binop_mma_kernel(const float* __restrict__ states,   // [8*2048, 32, 512]
                      const float* __restrict__ W,        // [128, 32, 64]
                      const float* __restrict__ b,        // [128, 32]
                      const int*   __restrict__ indices,  // [2048]
                      const int*   __restrict__ symbols,  // [2048]
                      const int*   __restrict__ args,     // [2048, 2]
                      float*       __restrict__ out)      // [2048, 32, 512]
{
    __shared__ float wh[DW * WPAD];                      // tf32(W[sym]), 8.7 KB
    __shared__ float bsh[DW];
    __shared__ __align__(16) float xstg[3][8 * XP];      // 3-stage x ring, 49.9 KB
                                                         // (reused as 16xTP transpose buf)

    const int n    = blockIdx.x;          // sample (one CTA per sample)
    const int t    = threadIdx.x;
    const int lane = t & 31;
    const int warp = t >> 5;              // 0..15: world cols warp*32..+31
    const int g    = lane >> 2;
    const int tig  = lane & 3;

    const int idx = indices[n];
    const int sym = symbols[n];
    const int a0  = args[2 * n];
    const int a1  = args[2 * n + 1];

    // x bases: full 512-world rows
    const float* xl = states + (size_t)(a0 * BATCH + idx) * (DW * NW);
    const float* xr = states + (size_t)(a1 * BATCH + idx) * (DW * NW);

    const int srow = t >> 6;           // staging row within chunk (0..7)
    const int scol = 4 * (t & 63);     // staging col (floats, 0..252)

    uint32_t xsb;
    {
        void* p = (void*)&xstg[0][srow * XP + scol];
        asm("{ .reg .u64 u; cvta.to.shared.u64 u, %1; cvt.u32.u64 %0, u; }"
            : "=r"(xsb) : "l"(p));
    }

    // issue chunk c into ring slot c%3 (2x cp.async 16B per thread)
    #define ISSUE(c_) do { \
        const float* s_ = ((c_) < 4) ? (xl + (size_t)(8 * (c_) + srow) * NW) \
                                     : (xr + (size_t)(8 * ((c_) - 4) + srow) * NW); \
        uint32_t d_ = xsb + ((c_) % 3) * (8 * XP * 4); \
        CP_ASYNC16(d_,        s_ + scol); \
        CP_ASYNC16(d_ + 1024, s_ + scol + 256); \
        CP_COMMIT(); \
    } while (0)

    // prologue: chunks 0,1 in flight
    ISSUE(0);
    ISSUE(1);

    // --- tf32(W[sym]) into padded smem (once per sample; overlaps async x) ---
    const float* Wp = W + (size_t)sym * (DW * K2D);
    #pragma unroll
    for (int i = 0; i < 4; i++) {
        int j  = t + 512 * i;
        int d  = j >> 6;
        int kk = j & 63;
        wh[d * WPAD + kk] = __uint_as_float(tf32_rna(Wp[j]));
    }
    if (t < DW) bsh[t] = b[sym * DW + t];

    float acc[2][4][4];
    #pragma unroll
    for (int mt = 0; mt < 2; mt++)
        #pragma unroll
        for (int nt = 0; nt < 4; nt++)
            #pragma unroll
            for (int r = 0; r < 4; r++) acc[mt][nt][r] = 0.f;

    const int fb = warp * 32 + g;      // fragment col base in staged chunk

    #pragma unroll
    for (int ks = 0; ks < 8; ks++) {
        // Drain rule: ks<7 -> "<=1 pending" proves chunk ks landed;
        // ks==7 -> the single pending group IS chunk 7 -> full drain.
        if (ks < 7) CP_WAIT1(); else CP_WAIT0();
        __syncthreads();               // all warps done with slot (ks+2)%3's old data
        if (ks + 2 < 8) ISSUE(ks + 2);

        const float* xb = xstg[ks % 3];

        // A(=x) fragments from smem (conflict-free LDS.32), tf32 round in regs
        uint32_t ah[2][4];
        #pragma unroll
        for (int mt = 0; mt < 2; mt++) {
            ah[mt][0] = tf32_rna(xb[tig * XP + fb + 16 * mt]);
            ah[mt][1] = tf32_rna(xb[tig * XP + fb + 16 * mt + 8]);
            ah[mt][2] = tf32_rna(xb[(tig + 4) * XP + fb + 16 * mt]);
            ah[mt][3] = tf32_rna(xb[(tig + 4) * XP + fb + 16 * mt + 8]);
        }

        // B(=W) loads + single-pass HMMA
        #pragma unroll
        for (int nt = 0; nt < 4; nt++) {
            const float* wp_ = wh + (nt * 8 + g) * WPAD + ks * 8 + tig;
            uint32_t bh0 = __float_as_uint(wp_[0]);
            uint32_t bh1 = __float_as_uint(wp_[4]);
            #pragma unroll
            for (int mt = 0; mt < 2; mt++)
                HMMA(acc[mt][nt], ah[mt][0], ah[mt][1], ah[mt][2], ah[mt][3], bh0, bh1);
        }
    }

    // --- epilogue: bias, L2-norm over d (quad shuffles), scale ---
    float2 bb[4];
    #pragma unroll
    for (int nt = 0; nt < 4; nt++)
        bb[nt] = *(const float2*)&bsh[nt * 8 + 2 * tig];

    #pragma unroll
    for (int mt = 0; mt < 2; mt++) {
        float s0 = 0.f, s1 = 0.f;    // world cols g, g+8 of this mtile
        #pragma unroll
        for (int nt = 0; nt < 4; nt++) {
            float y0 = acc[mt][nt][0] + bb[nt].x;
            float y1 = acc[mt][nt][1] + bb[nt].y;
            float y2 = acc[mt][nt][2] + bb[nt].x;
            float y3 = acc[mt][nt][3] + bb[nt].y;
            acc[mt][nt][0] = y0; acc[mt][nt][1] = y1;
            acc[mt][nt][2] = y2; acc[mt][nt][3] = y3;
            s0 = fmaf(y0, y0, fmaf(y1, y1, s0));
            s1 = fmaf(y2, y2, fmaf(y3, y3, s1));
        }
        s0 += __shfl_xor_sync(0xffffffffu, s0, 1);
        s0 += __shfl_xor_sync(0xffffffffu, s0, 2);
        s1 += __shfl_xor_sync(0xffffffffu, s1, 1);
        s1 += __shfl_xor_sync(0xffffffffu, s1, 2);
        const float r0 = rsqrtf(fmaxf(s0, 1e-12f));
        const float r1 = rsqrtf(fmaxf(s1, 1e-12f));
        #pragma unroll
        for (int nt = 0; nt < 4; nt++) {
            acc[mt][nt][0] *= r0;
            acc[mt][nt][1] *= r0;
            acc[mt][nt][2] *= r1;
            acc[mt][nt][3] *= r1;
        }
    }

    // --- store via smem transpose -> coalesced STG.128 ---
    // Reuse ring as 16 x TP buffer; two passes of 16 d-rows (pass p: nt=2p,2p+1)
    float* tb = &xstg[0][0];
    float* outb = out + (size_t)idx * (DW * NW);

    const int trow = t >> 5;           // reader: row (0..15)
    const int tcol = 4 * (t & 31);     // reader: float4 col base (0..124)

    #pragma unroll
    for (int p = 0; p < 2; p++) {
        __syncthreads();               // buffer free (mainloop or previous pass done)
        #pragma unroll
        for (int nn = 0; nn < 2; nn++) {
            const int rl = nn * 8 + 2 * tig;            // local d row in this pass
            const int nt = 2 * p + nn;
            const int cb = warp * 32 + g;
            // banks: 4*rl + cb ≡ 8*tig + g + const (mod 32) -> conflict-free
            tb[rl * TP + cb]            = acc[0][nt][0];
            tb[(rl + 1) * TP + cb]      = acc[0][nt][1];
            tb[rl * TP + cb + 8]        = acc[0][nt][2];
            tb[(rl + 1) * TP + cb + 8]  = acc[0][nt][3];
            tb[rl * TP + cb + 16]       = acc[1][nt][0];
            tb[(rl + 1) * TP + cb + 16] = acc[1][nt][1];
            tb[rl * TP + cb + 24]       = acc[1][nt][2];
            tb[(rl + 1) * TP + cb + 24] = acc[1][nt][3];
        }
        __syncthreads();
        // read rows coalesced, store STG.128 (each 8-lane group = one 128B line)
        #pragma unroll
        for (int j = 0; j < 4; j++) {
            float4 v = *(const float4*)&tb[trow * TP + tcol + 128 * j];
            *(float4*)(outb + (size_t)(p * 16 + trow) * NW + tcol + 128 * j) = v;
        }
    }
}

extern "C" void kernel_launch(void* const* d_in, const int* in_sizes, int n_in,
                              void* d_out, int out_size) {
    const float* states  = (const float*)d_in[0];
    const float* W       = (const float*)d_in[1];
    const float* b       = (const float*)d_in[2];
    const int*   indices = (const int*)d_in[3];
    const int*   symbols = (const int*)d_in[4];
    const int*   args    = (const int*)d_in[5];
    float*       out     = (float*)d_out;

    binop_mma_kernel<<<BATCH, 512>>>(states, W, b, indices, symbols, args, out);
}